// round 5
// baseline (speedup 1.0000x reference)
#include <cuda_runtime.h>
#include <cstdint>

#define NODES_MAX 100000
#define E_MAX     1600000

typedef unsigned long long ull;

// ---------------- device scratch (static, allocation-free) ----------------
__device__ float g_H[(size_t)NODES_MAX * 128];     // pre-aggregation h = (x*out_norm)@W
__device__ float g_AGG[(size_t)NODES_MAX * 128];   // aggregation result (128-wide layers)
__device__ float g_out_norm[NODES_MAX];
__device__ float g_in_norm[NODES_MAX];
__device__ int   g_odeg[NODES_MAX];
__device__ int   g_ideg[NODES_MAX];
__device__ int   g_row_beg[NODES_MAX];             // CSR segment start per dst node
__device__ int   g_fill[NODES_MAX];                // scatter cursors
__device__ int   g_csr_src[E_MAX];                 // src ids grouped by dst
__device__ int   g_alloc_ctr;                      // segment allocation cursor

// packed f32x2 fused multiply-add (sm_103a FFMA2; PTX-only)
#define FMA_F32X2(d, a, b, c) \
    asm("fma.rn.f32x2 %0, %1, %2, %3;" : "=l"(d) : "l"(a), "l"(b), "l"(c))

// ---------------- degree / norm ----------------
__global__ void k_init_deg(int n) {
    int i = blockIdx.x * blockDim.x + threadIdx.x;
    if (i < n) { g_odeg[i] = 1; g_ideg[i] = 1; }   // self-loop contributes 1 to each
    if (i == 0) g_alloc_ctr = 0;
}

__global__ void k_count_deg(const int* __restrict__ src, const int* __restrict__ dst, int E) {
    int i = blockIdx.x * blockDim.x + threadIdx.x;
    int st = gridDim.x * blockDim.x;
    for (; i < E; i += st) {
        atomicAdd(&g_odeg[src[i]], 1);
        atomicAdd(&g_ideg[dst[i]], 1);
    }
}

__global__ void k_norms(int n) {
    int i = blockIdx.x * blockDim.x + threadIdx.x;
    if (i < n) {
        g_out_norm[i] = rsqrtf((float)g_odeg[i]);
        g_in_norm[i]  = rsqrtf((float)g_ideg[i]);
    }
}

// ---------------- CSR segment allocation (order-free, fully parallel) ----------------
__global__ void __launch_bounds__(256)
k_alloc(int n) {
    __shared__ int warp_sums[8];
    __shared__ int block_base;
    int i    = blockIdx.x * 256 + threadIdx.x;
    int lane = threadIdx.x & 31;
    int wid  = threadIdx.x >> 5;
    int deg  = (i < n) ? (g_ideg[i] - 1) : 0;

    int v = deg;
#pragma unroll
    for (int off = 1; off < 32; off <<= 1) {
        int t = __shfl_up_sync(0xffffffffu, v, off);
        if (lane >= off) v += t;
    }
    if (lane == 31) warp_sums[wid] = v;
    __syncthreads();
    if (wid == 0) {
        int s = (lane < 8) ? warp_sums[lane] : 0;
#pragma unroll
        for (int off = 1; off < 8; off <<= 1) {
            int t = __shfl_up_sync(0xffffffffu, s, off);
            if (lane >= off) s += t;
        }
        if (lane < 8) warp_sums[lane] = s;
        if (lane == 7) block_base = atomicAdd(&g_alloc_ctr, s);
    }
    __syncthreads();
    int base = block_base + ((wid > 0) ? warp_sums[wid - 1] : 0) + (v - deg);
    if (i < n) { g_row_beg[i] = base; g_fill[i] = base; }
}

__global__ void k_scatter(const int* __restrict__ src, const int* __restrict__ dst, int E) {
    int i = blockIdx.x * blockDim.x + threadIdx.x;
    int st = gridDim.x * blockDim.x;
    for (; i < E; i += st) {
        int d = dst[i];
        int pos = atomicAdd(&g_fill[d], 1);
        g_csr_src[pos] = src[i];
    }
}

// ---------------- fused GEMM with packed f32x2 FMA ----------------
// H = X_eff @ W.  Accumulator lanes = (even-k partial, odd-k partial);
// horizontal add at the end. W staged pair-interleaved: wp[kp][c] =
// (W[2kp][c], W[2kp+1][c]).  X staged k-major so k-pairs are contiguous.
//   MODE 0: X_eff[r][k] = X[r][k] * out_norm[r]
//   MODE 1: X_eff[r][k] = relu(g_AGG[r][k]*in_norm[r] + bprev[k]) * out_norm[r]
template <int DOUT, int MODE>
__global__ void __launch_bounds__(256, 1)
k_gemm2(const float* __restrict__ X, const float* __restrict__ W,
        const float* __restrict__ bprev, int n)
{
    constexpr int NCI  = DOUT / 16;   // cols per thread (stride-16 assignment)
    constexpr int ROWS = 128;         // rows per block
    constexpr int XSS  = 134;         // xs row stride in floats (bank-split pad)

    extern __shared__ float sm[];
    ull*   wp = (ull*)sm;             // [64][DOUT] packed k-pairs
    float* xs = sm + 64 * DOUT * 2;   // [ROWS][XSS]

    const int t    = threadIdx.x;
    const int row0 = blockIdx.x * ROWS;

    // stage W pair-interleaved
    {
        float2* wp2 = (float2*)wp;
        for (int i = t; i < 64 * DOUT; i += 256) {
            int kp = i / DOUT, c = i - kp * DOUT;
            wp2[i] = make_float2(W[(2 * kp) * DOUT + c], W[(2 * kp + 1) * DOUT + c]);
        }
    }

    // stage X tile (previous layer's epilogue fused here)
    for (int i = t; i < ROWS * 32; i += 256) {
        int r  = i >> 5;
        int k4 = i & 31;
        int row = row0 + r;
        float4 v = make_float4(0.f, 0.f, 0.f, 0.f);
        if (row < n) {
            if (MODE == 0) {
                float on = g_out_norm[row];
                v = ((const float4*)X)[(size_t)row * 32 + k4];
                v.x *= on; v.y *= on; v.z *= on; v.w *= on;
            } else {
                float inn = g_in_norm[row];
                float on  = g_out_norm[row];
                float4 a  = ((const float4*)g_AGG)[(size_t)row * 32 + k4];
                float4 bb = ((const float4*)bprev)[k4];
                v.x = fmaxf(fmaf(a.x, inn, bb.x), 0.f) * on;
                v.y = fmaxf(fmaf(a.y, inn, bb.y), 0.f) * on;
                v.z = fmaxf(fmaf(a.z, inn, bb.z), 0.f) * on;
                v.w = fmaxf(fmaf(a.w, inn, bb.w), 0.f) * on;
            }
        }
        float2* p = (float2*)(xs + r * XSS + (k4 << 2));
        p[0] = make_float2(v.x, v.y);
        p[1] = make_float2(v.z, v.w);
    }
    __syncthreads();

    const int tx = t & 15;            // column base: cols tx + 16*ci
    const int rg = t >> 4;            // row group [0,16): rows rg*8 .. rg*8+7
    const float* xrow = xs + rg * 8 * XSS;
    const ull*   wpt  = wp + tx;

    ull acc[8][NCI];
#pragma unroll
    for (int r = 0; r < 8; r++)
#pragma unroll
        for (int ci = 0; ci < NCI; ci++) acc[r][ci] = 0ull;

#pragma unroll 2
    for (int kp = 0; kp < 64; kp++) {
        ull xv[8];
#pragma unroll
        for (int r = 0; r < 8; r++)
            xv[r] = *(const ull*)(xrow + r * XSS + kp * 2);
        ull wv[NCI];
#pragma unroll
        for (int ci = 0; ci < NCI; ci++)
            wv[ci] = wpt[kp * DOUT + 16 * ci];
#pragma unroll
        for (int r = 0; r < 8; r++)
#pragma unroll
            for (int ci = 0; ci < NCI; ci++)
                FMA_F32X2(acc[r][ci], xv[r], wv[ci], acc[r][ci]);
    }

    // horizontal add (even-k + odd-k lanes) and store
#pragma unroll
    for (int r = 0; r < 8; r++) {
        int row = row0 + rg * 8 + r;
        if (row < n) {
#pragma unroll
            for (int ci = 0; ci < NCI; ci++) {
                ull u = acc[r][ci];
                float lo = __uint_as_float((unsigned)(u & 0xffffffffull));
                float hi = __uint_as_float((unsigned)(u >> 32));
                g_H[(size_t)row * DOUT + tx + 16 * ci] = lo + hi;
            }
        }
    }
}

// ---------------- CSR gather-reduce aggregation ----------------
__global__ void __launch_bounds__(256)
k_agg128(int n) {
    int w    = (blockIdx.x * blockDim.x + threadIdx.x) >> 5;
    int lane = threadIdx.x & 31;
    if (w >= n) return;
    const float4* H4 = (const float4*)g_H;
    int beg = g_row_beg[w];
    int end = beg + g_ideg[w] - 1;
    float4 acc = H4[(size_t)w * 32 + lane];   // self-loop
    int j = beg;
    for (; j + 1 < end; j += 2) {
        int s0 = __ldg(&g_csr_src[j]);
        int s1 = __ldg(&g_csr_src[j + 1]);
        float4 v0 = H4[(size_t)s0 * 32 + lane];
        float4 v1 = H4[(size_t)s1 * 32 + lane];
        acc.x += v0.x; acc.y += v0.y; acc.z += v0.z; acc.w += v0.w;
        acc.x += v1.x; acc.y += v1.y; acc.z += v1.z; acc.w += v1.w;
    }
    if (j < end) {
        int s0 = __ldg(&g_csr_src[j]);
        float4 v0 = H4[(size_t)s0 * 32 + lane];
        acc.x += v0.x; acc.y += v0.y; acc.z += v0.z; acc.w += v0.w;
    }
    ((float4*)g_AGG)[(size_t)w * 32 + lane] = acc;
}

// 64-wide, final layer: half-warp per dst node; fuses out = acc*in_norm + b3.
__global__ void __launch_bounds__(256)
k_agg64_final(const float* __restrict__ b3, float* __restrict__ out, int n) {
    int gt   = blockIdx.x * blockDim.x + threadIdx.x;
    int lane = gt & 31;
    int w    = gt >> 5;
    int sub  = lane >> 4;
    int l16  = lane & 15;
    int node = w * 2 + sub;
    if (node >= n) return;
    const float4* H4 = (const float4*)g_H;
    int beg = g_row_beg[node];
    int end = beg + g_ideg[node] - 1;
    float4 acc = H4[(size_t)node * 16 + l16];  // self-loop
    int j = beg;
    for (; j + 1 < end; j += 2) {
        int s0 = __ldg(&g_csr_src[j]);
        int s1 = __ldg(&g_csr_src[j + 1]);
        float4 v0 = H4[(size_t)s0 * 16 + l16];
        float4 v1 = H4[(size_t)s1 * 16 + l16];
        acc.x += v0.x; acc.y += v0.y; acc.z += v0.z; acc.w += v0.w;
        acc.x += v1.x; acc.y += v1.y; acc.z += v1.z; acc.w += v1.w;
    }
    if (j < end) {
        int s0 = __ldg(&g_csr_src[j]);
        float4 v0 = H4[(size_t)s0 * 16 + l16];
        acc.x += v0.x; acc.y += v0.y; acc.z += v0.z; acc.w += v0.w;
    }
    float inn = g_in_norm[node];
    float4 bb = ((const float4*)b3)[l16];
    float4 o;
    o.x = fmaf(acc.x, inn, bb.x);
    o.y = fmaf(acc.y, inn, bb.y);
    o.z = fmaf(acc.z, inn, bb.z);
    o.w = fmaf(acc.w, inn, bb.w);
    ((float4*)out)[(size_t)node * 16 + l16] = o;
}

// ---------------- launcher ----------------
extern "C" void kernel_launch(void* const* d_in, const int* in_sizes, int n_in,
                              void* d_out, int out_size)
{
    const float* feat = (const float*)d_in[0];
    const int*   src  = (const int*)d_in[1];
    const int*   dst  = (const int*)d_in[2];
    const float* W1   = (const float*)d_in[3];
    const float* b1   = (const float*)d_in[4];
    const float* W2   = (const float*)d_in[5];
    const float* b2   = (const float*)d_in[6];
    const float* W3   = (const float*)d_in[7];
    const float* b3   = (const float*)d_in[8];
    float*       out  = (float*)d_out;

    const int n = in_sizes[0] / 128;   // 100000
    const int E = in_sizes[1];         // 1600000

    const int smem128 = 64 * 128 * 8 + 128 * 134 * 4;   // wp + xs = 134,144 B
    const int smem64  = 64 * 64 * 8 + 128 * 134 * 4;    // 101,376 B
    cudaFuncSetAttribute((const void*)k_gemm2<128, 0>,
                         cudaFuncAttributeMaxDynamicSharedMemorySize, smem128);
    cudaFuncSetAttribute((const void*)k_gemm2<128, 1>,
                         cudaFuncAttributeMaxDynamicSharedMemorySize, smem128);
    cudaFuncSetAttribute((const void*)k_gemm2<64, 1>,
                         cudaFuncAttributeMaxDynamicSharedMemorySize, smem64);

    // degrees + norms (self-loop via init=1)
    k_init_deg<<<(n + 255) / 256, 256>>>(n);
    k_count_deg<<<1024, 256>>>(src, dst, E);
    k_norms<<<(n + 255) / 256, 256>>>(n);

    // CSR build: parallel segment allocation + scatter (reused by all 3 layers)
    k_alloc<<<(n + 255) / 256, 256>>>(n);
    k_scatter<<<1024, 256>>>(src, dst, E);

    const int gblocks = (n + 127) / 128;

    // layer 1
    k_gemm2<128, 0><<<gblocks, 256, smem128>>>(feat, W1, nullptr, n);
    k_agg128<<<(n * 32 + 255) / 256, 256>>>(n);

    // layer 2
    k_gemm2<128, 1><<<gblocks, 256, smem128>>>(nullptr, W2, b1, n);
    k_agg128<<<(n * 32 + 255) / 256, 256>>>(n);

    // layer 3 (64-wide) + fused final epilogue straight to d_out
    k_gemm2<64, 1><<<gblocks, 256, smem64>>>(nullptr, W3, b2, n);
    k_agg64_final<<<(n * 16 + 255) / 256, 256>>>(b3, out, n);
}